// round 16
// baseline (speedup 1.0000x reference)
#include <cuda_runtime.h>
#include <cuda_fp16.h>
#include <math.h>
#include <stdint.h>

#define NUME     30000
#define NUMR     8
#define DIM_IN   128
#define DIM_OUT  128
#define DIM_R    64
#define DIM_T    32
#define HEADS    4
#define DHEAD    32
#define R_TOTAL  17
#define N_NODES  20000
#define N_EDGES  15000
#define BATCH    1024
#define DIN      160
#define KCLS     192
#define KC2      128                             // classifier GEMM K after rel split
#define NEG_SLOPE 0.2f
#define NPAD     30080

// zgemm config: A persistent (5 chunks) + 3 B buffers
#define ZCH      5
#define CHB      10240                           // bytes per chunk tile (128 rows x 80B)
#define NRB      3
#define NGRP     6
#define SMEM_Z   (ZCH * CHB + 3 * CHB)           // 81920 B

// classifier hgemm config (R13-style, K=128 -> 4 chunks)
#define NSTAGE   3
#define SMEM_GEMM (NSTAGE * 2 * CHB)             // 61440 B

// ---------------- scratch (device globals; no allocation allowed) ----------------
__device__ __align__(16) __half   g_x[(size_t)N_NODES * DIN];                  // [node][k] fp16
__device__ __align__(16) __half   g_z[(size_t)R_TOTAL * N_NODES * DIM_OUT];    // fp16 z
__device__ __align__(16) float    g_el[R_TOTAL * N_NODES * HEADS];
__device__ __align__(16) float    g_er[R_TOTAL * N_NODES * HEADS];
__device__ __align__(16) float    g_den[R_TOTAL * N_NODES * HEADS];
__device__ __align__(16) float    g_ex[R_TOTAL * N_EDGES * HEADS];
__device__ __align__(16) float    g_acc[N_NODES * DIM_OUT];
__device__ __align__(16) __half   g_A[2 * BATCH * KC2];                        // [row][k] fp16
__device__ __align__(16) __half   g_w[(size_t)2 * R_TOTAL * DIM_OUT * DIN];    // [lr][n][k] fp16
__device__ __align__(16) __half   g_cw[(size_t)2 * NPAD * KC2];                // [z][n][k] fp16 (emb part)
__device__ __align__(16) float    g_relp[(size_t)2 * NUMR * NUME];             // [z][q][n] fp32

__device__ __forceinline__ unsigned smem_u32(const void* p) {
    unsigned a;
    asm("{ .reg .u64 t; cvta.to.shared.u64 t, %1; cvt.u32.u64 %0, t; }" : "=r"(a) : "l"(p));
    return a;
}
__device__ __forceinline__ void ldsm4(uint32_t& r0, uint32_t& r1, uint32_t& r2, uint32_t& r3,
                                      unsigned addr) {
    asm volatile("ldmatrix.sync.aligned.m8n8.x4.shared.b16 {%0,%1,%2,%3}, [%4];"
                 : "=r"(r0), "=r"(r1), "=r"(r2), "=r"(r3) : "r"(addr));
}
__device__ __forceinline__ void cpa16(unsigned dst, const void* src, unsigned sz) {
    asm volatile("cp.async.cg.shared.global [%0], [%1], 16, %2;"
                 :: "r"(dst), "l"(src), "r"(sz));
}

// ---------------- prep kernels ----------------

__global__ void k_init(const int* __restrict__ node_ids,
                       const float* __restrict__ entity_emb,
                       const float* __restrict__ basis_freq,
                       const float* __restrict__ phase,
                       const int* __restrict__ ts_ptr) {
    long i = (long)blockIdx.x * blockDim.x + threadIdx.x;
    const long NA = (long)R_TOTAL * N_NODES * HEADS;
    const long NB = (long)N_NODES * DIM_OUT;
    if (i < NA) g_den[i] = 0.0f;
    if (i < NB) g_acc[i] = 0.0f;
    if (i >= (long)N_NODES * DIN) return;
    int n = (int)(i / DIN);
    int c = (int)(i % DIN);
    int nid = node_ids[n];
    float v;
    if (c < DIM_IN) {
        v = entity_emb[(long)(nid % NUME) * DIM_IN + c];
    } else {
        int ts = ts_ptr ? ts_ptr[0] : 31;
        float dt = (float)(ts - 1 - nid / NUME);
        int t = c - DIM_IN;
        v = cosf(dt * basis_freq[t] + phase[t]);
    }
    g_x[i] = __float2half_rn(v);
}

// fc_w [lr][k][n] -> g_w [lr][n][k] fp16
__global__ void k_prep_w(const float* __restrict__ fc_w) {
    long i = (long)blockIdx.x * blockDim.x + threadIdx.x;
    if (i >= (long)2 * R_TOTAL * DIN * DIM_OUT) return;
    int n = (int)(i % DIM_OUT);
    int k = (int)((i / DIM_OUT) % DIN);
    long lr = i / ((long)DIM_OUT * DIN);
    g_w[(lr * DIM_OUT + n) * DIN + k] = __float2half_rn(fc_w[i]);
}

// classifier W rows [0:128) -> g_cw [z][n][k] fp16, tiled transpose
__global__ void k_prep_cw(const float* __restrict__ sub_w, const float* __restrict__ obj_w) {
    __shared__ float tile[32][33];
    int z = blockIdx.z;
    const float* W = z == 0 ? sub_w : obj_w;
    int bn = blockIdx.x * 32;
    int bk = blockIdx.y * 32;       // 0..96
    int tx = threadIdx.x, ty = threadIdx.y;   // (32, 8)
#pragma unroll
    for (int j = 0; j < 4; j++) {
        int k = bk + ty + 8 * j;
        int n = bn + tx;
        tile[ty + 8 * j][tx] = (n < NUME) ? W[(long)k * NUME + n] : 0.f;
    }
    __syncthreads();
#pragma unroll
    for (int j = 0; j < 4; j++) {
        int n = bn + ty + 8 * j;
        int k = bk + tx;
        if (n < NPAD)
            g_cw[((long)z * NPAD + n) * KC2 + k] =
                __float2half_rn((n < NUME) ? tile[tx][ty + 8 * j] : 0.f);
    }
}

// rel projection: relp[z][q][n] = sum_k rel_emb[q][k] * W[128+k][n]  (fp32 exact)
// z=0 uses obj_rel_emb with sub_cls_w; z=1 uses sub_rel_emb with obj_cls_w
__global__ void k_relproj(const float* __restrict__ sub_w, const float* __restrict__ obj_w,
                          const float* __restrict__ sub_re, const float* __restrict__ obj_re) {
    __shared__ float re[NUMR * DIM_R];
    int z = blockIdx.y;
    const float* W = (z == 0) ? sub_w : obj_w;
    const float* R = (z == 0) ? obj_re : sub_re;
    for (int i = threadIdx.x; i < NUMR * DIM_R; i += blockDim.x) re[i] = R[i];
    __syncthreads();
    int n = blockIdx.x * blockDim.x + threadIdx.x;
    if (n >= NUME) return;
    float acc[NUMR];
#pragma unroll
    for (int q = 0; q < NUMR; q++) acc[q] = 0.f;
    for (int k = 0; k < DIM_R; k++) {
        float w = W[(long)(DIM_OUT + k) * NUME + n];
#pragma unroll
        for (int q = 0; q < NUMR; q++) acc[q] += re[q * DIM_R + k] * w;
    }
#pragma unroll
    for (int q = 0; q < NUMR; q++)
        g_relp[((long)z * NUMR + q) * NUME + n] = acc[q];
}

// ---------------- relation-batched z GEMM (R13) ----------------
__global__ __launch_bounds__(256, 2) void zgemm(
    const __half* __restrict__ X,
    const __half* __restrict__ Wl,
    __half* __restrict__ Z,
    const float* __restrict__ al, const float* __restrict__ ar,
    float* __restrict__ el, float* __restrict__ er) {
    extern __shared__ uint32_t smu[];
    const unsigned sbase = smem_u32(smu);
    const int bm = blockIdx.y * 128;
    const int r0 = blockIdx.z * NRB;
    const int cnt = (R_TOTAL - r0 < NRB) ? (R_TOTAL - r0) : NRB;
    const int T = cnt * ZCH;
    const int tid  = threadIdx.x;
    const int warp = tid >> 5;
    const int lane = tid & 31;
    const int wm = warp & 1;
    const int wn = warp >> 1;
    const int gid = lane >> 2;
    const int tig = lane & 3;

    const unsigned aoff = (unsigned)(((lane & 7) + ((lane >> 3) & 1) * 8) * 80 + (lane >> 4) * 16);
    const unsigned boff = (unsigned)(((lane & 7) + ((lane >> 4) & 1) * 8) * 80 + ((lane >> 3) & 1) * 16);

    const int r0_ = tid >> 2, c0_ = tid & 3;
    const int r1_ = (tid + 256) >> 2, c1_ = tid & 3;

#pragma unroll
    for (int c = 0; c < ZCH; c++) {
        unsigned ab = sbase + (unsigned)(c * CHB);
        cpa16(ab + (unsigned)(r0_ * 80 + c0_ * 16),
              X + (long)(bm + r0_) * DIN + c * 32 + c0_ * 8,
              (bm + r0_ < N_NODES) ? 16u : 0u);
        cpa16(ab + (unsigned)(r1_ * 80 + c1_ * 16),
              X + (long)(bm + r1_) * DIN + c * 32 + c1_ * 8,
              (bm + r1_ < N_NODES) ? 16u : 0u);
    }
    asm volatile("cp.async.commit_group;" ::: "memory");

    const unsigned bB = sbase + (unsigned)(ZCH * CHB);
    auto issueB = [&](int gc) {
        if (gc < T) {
            int rr = r0 + gc / ZCH, cc = gc % ZCH;
            unsigned bb = bB + (unsigned)((gc % 3) * CHB);
            const __half* W = Wl + ((long)rr * DIM_OUT) * DIN + cc * 32;
            cpa16(bb + (unsigned)(r0_ * 80 + c0_ * 16), W + (long)r0_ * DIN + c0_ * 8, 16u);
            cpa16(bb + (unsigned)(r1_ * 80 + c1_ * 16), W + (long)r1_ * DIN + c1_ * 8, 16u);
        }
        asm volatile("cp.async.commit_group;" ::: "memory");
    };
    issueB(0);
    issueB(1);

    float acc[4][4][4];
#pragma unroll
    for (int i = 0; i < 4; i++)
#pragma unroll
        for (int j = 0; j < 4; j++)
#pragma unroll
            for (int q = 0; q < 4; q++) acc[i][j][q] = 0.0f;

    for (int t = 0; t < T; t++) {
        asm volatile("cp.async.wait_group 1;" ::: "memory");
        __syncthreads();
        issueB(t + 2);

        const int ca = t % ZCH;
        const unsigned stA = sbase + (unsigned)(ca * CHB);
        const unsigned stB = bB + (unsigned)((t % 3) * CHB);
#pragma unroll
        for (int ks = 0; ks < 2; ks++) {
            const unsigned kb = (unsigned)(ks * 32);
            uint32_t af[4][4], bf[4][2];
#pragma unroll
            for (int mi = 0; mi < 4; mi++) {
                unsigned base = stA + (unsigned)((wm * 64 + mi * 16) * 80) + kb + aoff;
                ldsm4(af[mi][0], af[mi][1], af[mi][2], af[mi][3], base);
            }
            ldsm4(bf[0][0], bf[0][1], bf[1][0], bf[1][1],
                  stB + (unsigned)((wn * 32) * 80) + kb + boff);
            ldsm4(bf[2][0], bf[2][1], bf[3][0], bf[3][1],
                  stB + (unsigned)((wn * 32 + 16) * 80) + kb + boff);
#pragma unroll
            for (int mi = 0; mi < 4; mi++)
#pragma unroll
                for (int nj = 0; nj < 4; nj++) {
                    asm volatile(
                        "mma.sync.aligned.m16n8k16.row.col.f32.f16.f16.f32 "
                        "{%0,%1,%2,%3}, {%4,%5,%6,%7}, {%8,%9}, {%0,%1,%2,%3};"
                        : "+f"(acc[mi][nj][0]), "+f"(acc[mi][nj][1]),
                          "+f"(acc[mi][nj][2]), "+f"(acc[mi][nj][3])
                        : "r"(af[mi][0]), "r"(af[mi][1]), "r"(af[mi][2]), "r"(af[mi][3]),
                          "r"(bf[nj][0]), "r"(bf[nj][1]));
                }
        }

        if (ca == ZCH - 1) {
            int r = r0 + t / ZCH;
            __half* Ch = Z + (long)r * N_NODES * DIM_OUT;
            const float* alp = al + (long)r * HEADS * DHEAD + wn * DHEAD;
            const float* arp = ar + (long)r * HEADS * DHEAD + wn * DHEAD;
#pragma unroll
            for (int mi = 0; mi < 4; mi++) {
                int m0 = bm + wm * 64 + mi * 16 + gid;
                float sl0 = 0.f, sr0 = 0.f, sl1 = 0.f, sr1 = 0.f;
#pragma unroll
                for (int nj = 0; nj < 4; nj++) {
                    int n0 = wn * 32 + nj * 8 + tig * 2;
                    if (m0 < N_NODES)
                        *reinterpret_cast<__half2*>(&Ch[(long)m0 * DIM_OUT + n0]) =
                            __floats2half2_rn(acc[mi][nj][0], acc[mi][nj][1]);
                    if (m0 + 8 < N_NODES)
                        *reinterpret_cast<__half2*>(&Ch[(long)(m0 + 8) * DIM_OUT + n0]) =
                            __floats2half2_rn(acc[mi][nj][2], acc[mi][nj][3]);
                    int dh = nj * 8 + tig * 2;
                    float w0 = alp[dh], w1 = alp[dh + 1];
                    float v0 = arp[dh], v1 = arp[dh + 1];
                    sl0 += acc[mi][nj][0] * w0 + acc[mi][nj][1] * w1;
                    sr0 += acc[mi][nj][0] * v0 + acc[mi][nj][1] * v1;
                    sl1 += acc[mi][nj][2] * w0 + acc[mi][nj][3] * w1;
                    sr1 += acc[mi][nj][2] * v0 + acc[mi][nj][3] * v1;
                    acc[mi][nj][0] = acc[mi][nj][1] = acc[mi][nj][2] = acc[mi][nj][3] = 0.f;
                }
#pragma unroll
                for (int o = 1; o <= 2; o <<= 1) {
                    sl0 += __shfl_xor_sync(0xFFFFFFFFu, sl0, o);
                    sr0 += __shfl_xor_sync(0xFFFFFFFFu, sr0, o);
                    sl1 += __shfl_xor_sync(0xFFFFFFFFu, sl1, o);
                    sr1 += __shfl_xor_sync(0xFFFFFFFFu, sr1, o);
                }
                if (tig == 0) {
                    long base = (long)r * N_NODES;
                    if (m0 < N_NODES) {
                        el[(base + m0) * HEADS + wn] = sl0;
                        er[(base + m0) * HEADS + wn] = sr0;
                    }
                    if (m0 + 8 < N_NODES) {
                        el[(base + m0 + 8) * HEADS + wn] = sl1;
                        er[(base + m0 + 8) * HEADS + wn] = sr1;
                    }
                }
            }
        }
    }
}

// ---------------- classifier GEMM (K=128) + relp/bias epilogue ----------------
// C[z] (1024 x NUME) = A[z] (1024 x 128) @ B[z] (NPAD x 128)^T + bias_z + relp[z][rel[m]]
__global__ __launch_bounds__(256, 2) void hgemm_cls(
    const __half* __restrict__ Aall, long sA,
    const __half* __restrict__ Ball, long sB,
    float* __restrict__ Call, long sC,
    const float* __restrict__ bias0, const float* __restrict__ bias1,
    const int* __restrict__ rel, const float* __restrict__ relp) {
    extern __shared__ uint32_t smu[];
    const unsigned sbase = smem_u32(smu);
    const __half* A = Aall + sA * blockIdx.z;
    const __half* B = Ball + sB * blockIdx.z;
    float* C = Call + sC * blockIdx.z;
    const float* bias = (blockIdx.z == 0) ? bias0 : bias1;
    const float* rp = relp + (long)blockIdx.z * NUMR * NUME;
    const int bm = blockIdx.y * 128;
    const int bn = blockIdx.x * 128;
    const int tid  = threadIdx.x;
    const int warp = tid >> 5;
    const int lane = tid & 31;
    const int wm = warp & 1;
    const int wn = warp >> 1;
    const int gid = lane >> 2;
    const int tig = lane & 3;
    const int nchunks = KC2 >> 5;   // 4

    const unsigned aoff = (unsigned)(((lane & 7) + ((lane >> 3) & 1) * 8) * 80 + (lane >> 4) * 16);
    const unsigned boff = (unsigned)(((lane & 7) + ((lane >> 4) & 1) * 8) * 80 + ((lane >> 3) & 1) * 16);

    float acc[4][4][4];
#pragma unroll
    for (int i = 0; i < 4; i++)
#pragma unroll
        for (int j = 0; j < 4; j++)
#pragma unroll
            for (int q = 0; q < 4; q++) acc[i][j][q] = 0.0f;

    const int r0_ = tid >> 2, c0_ = tid & 3;
    const int r1_ = (tid + 256) >> 2, c1_ = tid & 3;

    auto issue = [&](int c) {
        if (c < nchunks) {
            unsigned ab = sbase + (unsigned)((c % NSTAGE) * 2 * CHB);
            unsigned bb = ab + CHB;
            int k0 = c << 5;
            cpa16(ab + (unsigned)(r0_ * 80 + c0_ * 16),
                  A + (long)(bm + r0_) * KC2 + k0 + c0_ * 8, 16u);
            cpa16(ab + (unsigned)(r1_ * 80 + c1_ * 16),
                  A + (long)(bm + r1_) * KC2 + k0 + c1_ * 8, 16u);
            cpa16(bb + (unsigned)(r0_ * 80 + c0_ * 16),
                  B + (long)(bn + r0_) * KC2 + k0 + c0_ * 8, 16u);
            cpa16(bb + (unsigned)(r1_ * 80 + c1_ * 16),
                  B + (long)(bn + r1_) * KC2 + k0 + c1_ * 8, 16u);
        }
        asm volatile("cp.async.commit_group;" ::: "memory");
    };
    issue(0);
    issue(1);

    for (int c = 0; c < nchunks; c++) {
        asm volatile("cp.async.wait_group 1;" ::: "memory");
        __syncthreads();
        issue(c + 2);

        const unsigned stA = sbase + (unsigned)((c % NSTAGE) * 2 * CHB);
        const unsigned stB = stA + CHB;
#pragma unroll
        for (int ks = 0; ks < 2; ks++) {
            const unsigned kb = (unsigned)(ks * 32);
            uint32_t af[4][4], bf[4][2];
#pragma unroll
            for (int mi = 0; mi < 4; mi++) {
                unsigned base = stA + (unsigned)((wm * 64 + mi * 16) * 80) + kb + aoff;
                ldsm4(af[mi][0], af[mi][1], af[mi][2], af[mi][3], base);
            }
            ldsm4(bf[0][0], bf[0][1], bf[1][0], bf[1][1],
                  stB + (unsigned)((wn * 32) * 80) + kb + boff);
            ldsm4(bf[2][0], bf[2][1], bf[3][0], bf[3][1],
                  stB + (unsigned)((wn * 32 + 16) * 80) + kb + boff);
#pragma unroll
            for (int mi = 0; mi < 4; mi++)
#pragma unroll
                for (int nj = 0; nj < 4; nj++) {
                    asm volatile(
                        "mma.sync.aligned.m16n8k16.row.col.f32.f16.f16.f32 "
                        "{%0,%1,%2,%3}, {%4,%5,%6,%7}, {%8,%9}, {%0,%1,%2,%3};"
                        : "+f"(acc[mi][nj][0]), "+f"(acc[mi][nj][1]),
                          "+f"(acc[mi][nj][2]), "+f"(acc[mi][nj][3])
                        : "r"(af[mi][0]), "r"(af[mi][1]), "r"(af[mi][2]), "r"(af[mi][3]),
                          "r"(bf[nj][0]), "r"(bf[nj][1]));
                }
        }
    }

    // epilogue: + bias + relp[rel[m]]
#pragma unroll
    for (int mi = 0; mi < 4; mi++) {
        int m0 = bm + wm * 64 + mi * 16 + gid;
        const float* rp0 = rp + (long)rel[m0] * NUME;
        const float* rp1 = rp + (long)rel[m0 + 8] * NUME;
#pragma unroll
        for (int nj = 0; nj < 4; nj++) {
            int n0 = bn + wn * 32 + nj * 8 + tig * 2;
            if (n0 < NUME) {
                float b0 = bias[n0];
                float b1 = bias[n0 + 1];
                C[(long)m0 * NUME + n0]     = acc[mi][nj][0] + b0 + rp0[n0];
                C[(long)m0 * NUME + n0 + 1] = acc[mi][nj][1] + b1 + rp0[n0 + 1];
                C[(long)(m0 + 8) * NUME + n0]     = acc[mi][nj][2] + b0 + rp1[n0];
                C[(long)(m0 + 8) * NUME + n0 + 1] = acc[mi][nj][3] + b1 + rp1[n0 + 1];
            }
        }
    }
}

// ---------------- edge kernels ----------------
// Softmax is shift-invariant; |e| is O(1) here so no max-subtraction needed.

__global__ void k_edge_ex(const int* __restrict__ src, const int* __restrict__ dst) {
    long i = (long)blockIdx.x * blockDim.x + threadIdx.x;
    if (i >= (long)R_TOTAL * N_EDGES * HEADS) return;
    int h = (int)(i % HEADS);
    int e = (int)((i / HEADS) % N_EDGES);
    int r = (int)(i / ((long)HEADS * N_EDGES));
    int s = src[r * N_EDGES + e];
    int d = dst[r * N_EDGES + e];
    float ev = g_el[((long)r * N_NODES + s) * HEADS + h] +
               g_er[((long)r * N_NODES + d) * HEADS + h];
    ev = (ev >= 0.f) ? ev : NEG_SLOPE * ev;
    float ex = expf(ev);
    g_ex[i] = ex;
    atomicAdd(&g_den[((long)r * N_NODES + d) * HEADS + h], ex);
}

__global__ void k_msg(const int* __restrict__ src, const int* __restrict__ dst) {
    long gw = ((long)blockIdx.x * blockDim.x + threadIdx.x) >> 5;
    int lane = threadIdx.x & 31;
    if (gw >= (long)R_TOTAL * N_EDGES) return;
    int r = (int)(gw / N_EDGES);
    int e = (int)(gw % N_EDGES);
    int s = src[r * N_EDGES + e];
    int d = dst[r * N_EDGES + e];
    int c0 = lane * 4;
    int h = lane >> 3;
    float ex  = g_ex[gw * HEADS + h];
    float den = fmaxf(g_den[((long)r * N_NODES + d) * HEADS + h], 1e-9f);
    float a = ex / den;
    uint2 zu = *reinterpret_cast<const uint2*>(&g_z[((long)r * N_NODES + s) * DIM_OUT + c0]);
    float2 z01 = __half22float2(*reinterpret_cast<__half2*>(&zu.x));
    float2 z23 = __half22float2(*reinterpret_cast<__half2*>(&zu.y));
    float* p = &g_acc[(long)d * DIM_OUT + c0];
    asm volatile("red.global.add.v4.f32 [%0], {%1,%2,%3,%4};"
                 :: "l"(p), "f"(a * z01.x), "f"(a * z01.y), "f"(a * z23.x), "f"(a * z23.y)
                 : "memory");
}

// relu(mean) -> g_x fp16; ALSO zeroes state for the next layer
__global__ void k_finalize() {
    long i = (long)blockIdx.x * blockDim.x + threadIdx.x;
    const long NA = (long)R_TOTAL * N_NODES * HEADS;
    if (i < NA) g_den[i] = 0.0f;
    if (i >= (long)N_NODES * DIM_OUT) return;
    int n = (int)(i / DIM_OUT);
    int c = (int)(i % DIM_OUT);
    float v = g_acc[i] * (1.0f / (float)R_TOTAL);
    g_acc[i] = 0.0f;
    v = (v > 0.f) ? v : 0.f;
    g_x[(long)n * DIN + c] = __float2half_rn(v);
}

// classifier A matrices (fp16, K=128): pure embedding gather
__global__ void k_buildA(const int* __restrict__ root_idx) {
    long i = (long)blockIdx.x * blockDim.x + threadIdx.x;
    if (i >= (long)2 * BATCH * KC2) return;
    int k = (int)(i % KC2);
    int row = (int)(i / KC2);
    int z = row >> 10;          // 0 = sub_pred (obj emb), 1 = obj_pred (sub emb)
    int b = row & 1023;
    int node = root_idx[z == 0 ? BATCH + b : b];
    g_A[i] = g_x[(long)node * DIN + k];
}

// ---------------- launch ----------------
extern "C" void kernel_launch(void* const* d_in, const int* in_sizes, int n_in,
                              void* d_out, int out_size) {
    const int*   node_ids    = (const int*)d_in[0];
    const int*   edge_src    = (const int*)d_in[1];
    const int*   edge_dst    = (const int*)d_in[2];
    const int*   root_idx    = (const int*)d_in[3];
    const int*   rel         = (const int*)d_in[4];
    const float* entity_emb  = (const float*)d_in[5];
    const float* basis_freq  = (const float*)d_in[6];
    const float* phase       = (const float*)d_in[7];
    const float* fc_w        = (const float*)d_in[8];
    const float* attn_l      = (const float*)d_in[9];
    const float* attn_r      = (const float*)d_in[10];
    const float* sub_rel_emb = (const float*)d_in[11];
    const float* obj_rel_emb = (const float*)d_in[12];
    const float* sub_cls_w   = (const float*)d_in[13];
    const float* sub_cls_b   = (const float*)d_in[14];
    const float* obj_cls_w   = (const float*)d_in[15];
    const float* obj_cls_b   = (const float*)d_in[16];
    const int*   ts_ptr      = (n_in > 17) ? (const int*)d_in[17] : nullptr;

    float* out = (float*)d_out;

    __half *px, *pA, *pw, *pcw, *pz;
    float *pel, *per, *prelp;
    cudaGetSymbolAddress((void**)&px, g_x);
    cudaGetSymbolAddress((void**)&pz, g_z);
    cudaGetSymbolAddress((void**)&pA, g_A);
    cudaGetSymbolAddress((void**)&pel, g_el);
    cudaGetSymbolAddress((void**)&per, g_er);
    cudaGetSymbolAddress((void**)&pw, g_w);
    cudaGetSymbolAddress((void**)&pcw, g_cw);
    cudaGetSymbolAddress((void**)&prelp, g_relp);

    static int smem_set = 0;
    if (!smem_set) {
        cudaFuncSetAttribute(zgemm, cudaFuncAttributeMaxDynamicSharedMemorySize, SMEM_Z);
        cudaFuncSetAttribute(hgemm_cls, cudaFuncAttributeMaxDynamicSharedMemorySize, SMEM_GEMM);
        smem_set = 1;
    }

    const int TB = 256;
    long n_init = (long)N_NODES * DIN;
    k_init<<<(unsigned)((n_init + TB - 1) / TB), TB>>>(node_ids, entity_emb, basis_freq, phase, ts_ptr);
    long n_pw = (long)2 * R_TOTAL * DIN * DIM_OUT;
    k_prep_w<<<(unsigned)((n_pw + TB - 1) / TB), TB>>>(fc_w);
    dim3 gcw(NPAD / 32, KC2 / 32, 2);
    k_prep_cw<<<gcw, dim3(32, 8)>>>(sub_cls_w, obj_cls_w);
    dim3 grp((NUME + TB - 1) / TB, 2, 1);
    k_relproj<<<grp, TB>>>(sub_cls_w, obj_cls_w, sub_rel_emb, obj_rel_emb);

    const long n_edgehead = (long)R_TOTAL * N_EDGES * HEADS;
    const long n_zero     = (long)N_NODES * DIM_OUT;
    const long n_msgw     = (long)R_TOTAL * N_EDGES * 32;

    for (int l = 0; l < 2; l++) {
        dim3 gz(1, (N_NODES + 127) / 128, NGRP);
        zgemm<<<gz, 256, SMEM_Z>>>(px,
                            pw + (long)l * R_TOTAL * DIM_OUT * DIN,
                            pz,
                            attn_l + (long)l * R_TOTAL * HEADS * DHEAD,
                            attn_r + (long)l * R_TOTAL * HEADS * DHEAD,
                            pel, per);

        k_edge_ex<<<(unsigned)((n_edgehead + TB - 1) / TB), TB>>>(edge_src, edge_dst);
        k_msg<<<(unsigned)((n_msgw + TB - 1) / TB), TB>>>(edge_src, edge_dst);

        k_finalize<<<(unsigned)((n_zero + TB - 1) / TB), TB>>>();
    }

    long n_bA = (long)2 * BATCH * KC2;
    k_buildA<<<(unsigned)((n_bA + TB - 1) / TB), TB>>>(root_idx);

    // classifier: K=128, both z in one launch; grid (235, 8, 2)
    dim3 gc(NPAD / 128, BATCH / 128, 2);
    hgemm_cls<<<gc, 256, SMEM_GEMM>>>(pA, (long)BATCH * KC2,
                        pcw, (long)NPAD * KC2,
                        out, (long)BATCH * NUME,
                        sub_cls_b, obj_cls_b, rel, prelp);
    (void)in_sizes; (void)out_size;
}

// round 17
// speedup vs baseline: 1.0589x; 1.0589x over previous
#include <cuda_runtime.h>
#include <cuda_fp16.h>
#include <math.h>
#include <stdint.h>

#define NUME     30000
#define NUMR     8
#define DIM_IN   128
#define DIM_OUT  128
#define DIM_R    64
#define DIM_T    32
#define HEADS    4
#define DHEAD    32
#define R_TOTAL  17
#define N_NODES  20000
#define N_EDGES  15000
#define BATCH    1024
#define DIN      160
#define KCLS     (DIM_OUT + DIM_R)   // 192
#define NEG_SLOPE 0.2f
#define NPAD     30080

// classifier hgemm config (R11-best)
#define NSTAGE   3
#define AS       20                              // b32 per smem row (16 data + 4 pad)
#define STAGE_B32 (256 * AS)
#define SMEM_GEMM (NSTAGE * STAGE_B32 * 4)       // 61440 B

// zgemm config: A persistent (5 chunks) + 3 B buffers
#define ZCH      5                               // K chunks (160/32)
#define CHB      10240                           // bytes per chunk tile (128 rows x 80B)
#define NRB      3                               // relations per CTA group
#define NGRP     6                               // ceil(17/3)
#define SMEM_Z   (ZCH * CHB + 3 * CHB)           // 81920 B

// ---------------- scratch (device globals; no allocation allowed) ----------------
__device__ __align__(16) __half   g_x[(size_t)N_NODES * DIN];                  // [node][k] fp16
__device__ __align__(16) __half   g_z[(size_t)R_TOTAL * N_NODES * DIM_OUT];    // fp16 z
__device__ __align__(16) float    g_el[R_TOTAL * N_NODES * HEADS];
__device__ __align__(16) float    g_er[R_TOTAL * N_NODES * HEADS];
__device__ __align__(16) float    g_den[R_TOTAL * N_NODES * HEADS];
__device__ __align__(16) float    g_ex[R_TOTAL * N_EDGES * HEADS];
__device__ __align__(16) float    g_acc[N_NODES * DIM_OUT];
__device__ __align__(16) __half   g_A[2 * BATCH * KCLS];                       // [row][k] fp16
__device__ __align__(16) __half   g_w[(size_t)2 * R_TOTAL * DIM_OUT * DIN];    // [lr][n][k] fp16
__device__ __align__(16) __half   g_cw[(size_t)2 * NPAD * KCLS];               // [z][n][k] fp16

__device__ __forceinline__ unsigned smem_u32(const void* p) {
    unsigned a;
    asm("{ .reg .u64 t; cvta.to.shared.u64 t, %1; cvt.u32.u64 %0, t; }" : "=r"(a) : "l"(p));
    return a;
}
__device__ __forceinline__ void ldsm4(uint32_t& r0, uint32_t& r1, uint32_t& r2, uint32_t& r3,
                                      unsigned addr) {
    asm volatile("ldmatrix.sync.aligned.m8n8.x4.shared.b16 {%0,%1,%2,%3}, [%4];"
                 : "=r"(r0), "=r"(r1), "=r"(r2), "=r"(r3) : "r"(addr));
}
__device__ __forceinline__ void cpa16(unsigned dst, const void* src, unsigned sz) {
    asm volatile("cp.async.cg.shared.global [%0], [%1], 16, %2;"
                 :: "r"(dst), "l"(src), "r"(sz));
}
__device__ __forceinline__ void stg_cs_v2(float* p, float a, float b) {
    asm volatile("st.global.cs.v2.f32 [%0], {%1,%2};" :: "l"(p), "f"(a), "f"(b) : "memory");
}

// ---------------- prep kernels ----------------

__global__ void k_init(const int* __restrict__ node_ids,
                       const float* __restrict__ entity_emb,
                       const float* __restrict__ basis_freq,
                       const float* __restrict__ phase,
                       const int* __restrict__ ts_ptr) {
    long i = (long)blockIdx.x * blockDim.x + threadIdx.x;
    const long NA = (long)R_TOTAL * N_NODES * HEADS;
    const long NB = (long)N_NODES * DIM_OUT;
    if (i < NA) g_den[i] = 0.0f;
    if (i < NB) g_acc[i] = 0.0f;
    if (i >= (long)N_NODES * DIN) return;
    int n = (int)(i / DIN);
    int c = (int)(i % DIN);
    int nid = node_ids[n];
    float v;
    if (c < DIM_IN) {
        v = entity_emb[(long)(nid % NUME) * DIM_IN + c];
    } else {
        int ts = ts_ptr ? ts_ptr[0] : 31;
        float dt = (float)(ts - 1 - nid / NUME);
        int t = c - DIM_IN;
        v = cosf(dt * basis_freq[t] + phase[t]);
    }
    g_x[i] = __float2half_rn(v);
}

// fc_w [lr][k][n] -> g_w [lr][n][k] fp16
__global__ void k_prep_w(const float* __restrict__ fc_w) {
    long i = (long)blockIdx.x * blockDim.x + threadIdx.x;
    if (i >= (long)2 * R_TOTAL * DIN * DIM_OUT) return;
    int n = (int)(i % DIM_OUT);
    int k = (int)((i / DIM_OUT) % DIN);
    long lr = i / ((long)DIM_OUT * DIN);
    g_w[(lr * DIM_OUT + n) * DIN + k] = __float2half_rn(fc_w[i]);
}

// classifier W [192][30000] -> g_cw [z][n][k] fp16, tiled transpose
__global__ void k_prep_cw(const float* __restrict__ sub_w, const float* __restrict__ obj_w) {
    __shared__ float tile[32][33];
    int z = blockIdx.z;
    const float* W = z == 0 ? sub_w : obj_w;
    int bn = blockIdx.x * 32;
    int bk = blockIdx.y * 32;
    int tx = threadIdx.x, ty = threadIdx.y;   // (32, 8)
#pragma unroll
    for (int j = 0; j < 4; j++) {
        int k = bk + ty + 8 * j;
        int n = bn + tx;
        tile[ty + 8 * j][tx] = (n < NUME) ? W[(long)k * NUME + n] : 0.f;
    }
    __syncthreads();
#pragma unroll
    for (int j = 0; j < 4; j++) {
        int n = bn + ty + 8 * j;
        int k = bk + tx;
        if (n < NPAD)
            g_cw[((long)z * NPAD + n) * KCLS + k] =
                __float2half_rn((n < NUME) ? tile[tx][ty + 8 * j] : 0.f);
    }
}

// ---------------- relation-batched z GEMM (R13) ----------------
__global__ __launch_bounds__(256, 2) void zgemm(
    const __half* __restrict__ X,
    const __half* __restrict__ Wl,
    __half* __restrict__ Z,
    const float* __restrict__ al, const float* __restrict__ ar,
    float* __restrict__ el, float* __restrict__ er) {
    extern __shared__ uint32_t smu[];
    const unsigned sbase = smem_u32(smu);
    const int bm = blockIdx.y * 128;
    const int r0 = blockIdx.z * NRB;
    const int cnt = (R_TOTAL - r0 < NRB) ? (R_TOTAL - r0) : NRB;
    const int T = cnt * ZCH;
    const int tid  = threadIdx.x;
    const int warp = tid >> 5;
    const int lane = tid & 31;
    const int wm = warp & 1;
    const int wn = warp >> 1;
    const int gid = lane >> 2;
    const int tig = lane & 3;

    const unsigned aoff = (unsigned)(((lane & 7) + ((lane >> 3) & 1) * 8) * 80 + (lane >> 4) * 16);
    const unsigned boff = (unsigned)(((lane & 7) + ((lane >> 4) & 1) * 8) * 80 + ((lane >> 3) & 1) * 16);

    const int r0_ = tid >> 2, c0_ = tid & 3;
    const int r1_ = (tid + 256) >> 2, c1_ = tid & 3;

#pragma unroll
    for (int c = 0; c < ZCH; c++) {
        unsigned ab = sbase + (unsigned)(c * CHB);
        cpa16(ab + (unsigned)(r0_ * 80 + c0_ * 16),
              X + (long)(bm + r0_) * DIN + c * 32 + c0_ * 8,
              (bm + r0_ < N_NODES) ? 16u : 0u);
        cpa16(ab + (unsigned)(r1_ * 80 + c1_ * 16),
              X + (long)(bm + r1_) * DIN + c * 32 + c1_ * 8,
              (bm + r1_ < N_NODES) ? 16u : 0u);
    }
    asm volatile("cp.async.commit_group;" ::: "memory");

    const unsigned bB = sbase + (unsigned)(ZCH * CHB);
    auto issueB = [&](int gc) {
        if (gc < T) {
            int rr = r0 + gc / ZCH, cc = gc % ZCH;
            unsigned bb = bB + (unsigned)((gc % 3) * CHB);
            const __half* W = Wl + ((long)rr * DIM_OUT) * DIN + cc * 32;
            cpa16(bb + (unsigned)(r0_ * 80 + c0_ * 16), W + (long)r0_ * DIN + c0_ * 8, 16u);
            cpa16(bb + (unsigned)(r1_ * 80 + c1_ * 16), W + (long)r1_ * DIN + c1_ * 8, 16u);
        }
        asm volatile("cp.async.commit_group;" ::: "memory");
    };
    issueB(0);
    issueB(1);

    float acc[4][4][4];
#pragma unroll
    for (int i = 0; i < 4; i++)
#pragma unroll
        for (int j = 0; j < 4; j++)
#pragma unroll
            for (int q = 0; q < 4; q++) acc[i][j][q] = 0.0f;

    for (int t = 0; t < T; t++) {
        asm volatile("cp.async.wait_group 1;" ::: "memory");
        __syncthreads();
        issueB(t + 2);

        const int ca = t % ZCH;
        const unsigned stA = sbase + (unsigned)(ca * CHB);
        const unsigned stB = bB + (unsigned)((t % 3) * CHB);
#pragma unroll
        for (int ks = 0; ks < 2; ks++) {
            const unsigned kb = (unsigned)(ks * 32);
            uint32_t af[4][4], bf[4][2];
#pragma unroll
            for (int mi = 0; mi < 4; mi++) {
                unsigned base = stA + (unsigned)((wm * 64 + mi * 16) * 80) + kb + aoff;
                ldsm4(af[mi][0], af[mi][1], af[mi][2], af[mi][3], base);
            }
            ldsm4(bf[0][0], bf[0][1], bf[1][0], bf[1][1],
                  stB + (unsigned)((wn * 32) * 80) + kb + boff);
            ldsm4(bf[2][0], bf[2][1], bf[3][0], bf[3][1],
                  stB + (unsigned)((wn * 32 + 16) * 80) + kb + boff);
#pragma unroll
            for (int mi = 0; mi < 4; mi++)
#pragma unroll
                for (int nj = 0; nj < 4; nj++) {
                    asm volatile(
                        "mma.sync.aligned.m16n8k16.row.col.f32.f16.f16.f32 "
                        "{%0,%1,%2,%3}, {%4,%5,%6,%7}, {%8,%9}, {%0,%1,%2,%3};"
                        : "+f"(acc[mi][nj][0]), "+f"(acc[mi][nj][1]),
                          "+f"(acc[mi][nj][2]), "+f"(acc[mi][nj][3])
                        : "r"(af[mi][0]), "r"(af[mi][1]), "r"(af[mi][2]), "r"(af[mi][3]),
                          "r"(bf[nj][0]), "r"(bf[nj][1]));
                }
        }

        if (ca == ZCH - 1) {
            int r = r0 + t / ZCH;
            __half* Ch = Z + (long)r * N_NODES * DIM_OUT;
            const float* alp = al + (long)r * HEADS * DHEAD + wn * DHEAD;
            const float* arp = ar + (long)r * HEADS * DHEAD + wn * DHEAD;
#pragma unroll
            for (int mi = 0; mi < 4; mi++) {
                int m0 = bm + wm * 64 + mi * 16 + gid;
                float sl0 = 0.f, sr0 = 0.f, sl1 = 0.f, sr1 = 0.f;
#pragma unroll
                for (int nj = 0; nj < 4; nj++) {
                    int n0 = wn * 32 + nj * 8 + tig * 2;
                    if (m0 < N_NODES)
                        *reinterpret_cast<__half2*>(&Ch[(long)m0 * DIM_OUT + n0]) =
                            __floats2half2_rn(acc[mi][nj][0], acc[mi][nj][1]);
                    if (m0 + 8 < N_NODES)
                        *reinterpret_cast<__half2*>(&Ch[(long)(m0 + 8) * DIM_OUT + n0]) =
                            __floats2half2_rn(acc[mi][nj][2], acc[mi][nj][3]);
                    int dh = nj * 8 + tig * 2;
                    float w0 = alp[dh], w1 = alp[dh + 1];
                    float v0 = arp[dh], v1 = arp[dh + 1];
                    sl0 += acc[mi][nj][0] * w0 + acc[mi][nj][1] * w1;
                    sr0 += acc[mi][nj][0] * v0 + acc[mi][nj][1] * v1;
                    sl1 += acc[mi][nj][2] * w0 + acc[mi][nj][3] * w1;
                    sr1 += acc[mi][nj][2] * v0 + acc[mi][nj][3] * v1;
                    acc[mi][nj][0] = acc[mi][nj][1] = acc[mi][nj][2] = acc[mi][nj][3] = 0.f;
                }
#pragma unroll
                for (int o = 1; o <= 2; o <<= 1) {
                    sl0 += __shfl_xor_sync(0xFFFFFFFFu, sl0, o);
                    sr0 += __shfl_xor_sync(0xFFFFFFFFu, sr0, o);
                    sl1 += __shfl_xor_sync(0xFFFFFFFFu, sl1, o);
                    sr1 += __shfl_xor_sync(0xFFFFFFFFu, sr1, o);
                }
                if (tig == 0) {
                    long base = (long)r * N_NODES;
                    if (m0 < N_NODES) {
                        el[(base + m0) * HEADS + wn] = sl0;
                        er[(base + m0) * HEADS + wn] = sr0;
                    }
                    if (m0 + 8 < N_NODES) {
                        el[(base + m0 + 8) * HEADS + wn] = sl1;
                        er[(base + m0 + 8) * HEADS + wn] = sr1;
                    }
                }
            }
        }
    }
}

// ---------------- classifier fp16 tensor-core GEMM (R11 config + streaming stores) ----------------
__global__ __launch_bounds__(256, 2) void hgemm(
    const __half* __restrict__ Aall, long sA,
    const __half* __restrict__ Ball, long sB,
    float* __restrict__ Call, long sC,
    const float* __restrict__ bias0, const float* __restrict__ bias1,
    int M, int N, int K) {
    extern __shared__ uint32_t smu[];
    const unsigned sbase = smem_u32(smu);
    const __half* A = Aall + sA * blockIdx.z;
    const __half* B = Ball + sB * blockIdx.z;
    float* C = Call + sC * blockIdx.z;
    const float* bias = (blockIdx.z == 0) ? bias0 : bias1;
    const int bm = blockIdx.y * 128;
    const int bn = blockIdx.x * 128;
    const int tid  = threadIdx.x;
    const int warp = tid >> 5;
    const int lane = tid & 31;
    const int wm = warp & 1;
    const int wn = warp >> 1;
    const int gid = lane >> 2;
    const int tig = lane & 3;
    const int nchunks = K >> 5;

    const unsigned aoff = (unsigned)(((lane & 7) + ((lane >> 3) & 1) * 8) * 80 + (lane >> 4) * 16);
    const unsigned boff = (unsigned)(((lane & 7) + ((lane >> 4) & 1) * 8) * 80 + ((lane >> 3) & 1) * 16);

    float acc[4][4][4];
#pragma unroll
    for (int i = 0; i < 4; i++)
#pragma unroll
        for (int j = 0; j < 4; j++)
#pragma unroll
            for (int q = 0; q < 4; q++) acc[i][j][q] = 0.0f;

    const int r0 = tid >> 2, c0 = tid & 3;
    const int r1 = (tid + 256) >> 2, c1 = tid & 3;

    auto issue = [&](int c) {
        if (c < nchunks) {
            unsigned ab = sbase + (unsigned)((c % NSTAGE) * STAGE_B32) * 4u;
            unsigned bb = ab + 128u * AS * 4u;
            int k0 = c << 5;
            cpa16(ab + (unsigned)(r0 * AS + c0 * 4) * 4u,
                  A + (long)(bm + r0) * K + k0 + c0 * 8, (bm + r0 < M) ? 16u : 0u);
            cpa16(ab + (unsigned)(r1 * AS + c1 * 4) * 4u,
                  A + (long)(bm + r1) * K + k0 + c1 * 8, (bm + r1 < M) ? 16u : 0u);
            cpa16(bb + (unsigned)(r0 * AS + c0 * 4) * 4u,
                  B + (long)(bn + r0) * K + k0 + c0 * 8, (bn + r0 < N) ? 16u : 0u);
            cpa16(bb + (unsigned)(r1 * AS + c1 * 4) * 4u,
                  B + (long)(bn + r1) * K + k0 + c1 * 8, (bn + r1 < N) ? 16u : 0u);
        }
        asm volatile("cp.async.commit_group;" ::: "memory");
    };
    issue(0);
    issue(1);

    for (int c = 0; c < nchunks; c++) {
        asm volatile("cp.async.wait_group 1;" ::: "memory");
        __syncthreads();
        issue(c + 2);

        const unsigned stA = sbase + (unsigned)((c % NSTAGE) * STAGE_B32) * 4u;
        const unsigned stB = stA + 128u * AS * 4u;
#pragma unroll
        for (int ks = 0; ks < 2; ks++) {
            const unsigned kb = (unsigned)(ks * 32);
            uint32_t af[4][4], bf[4][2];
#pragma unroll
            for (int mi = 0; mi < 4; mi++) {
                unsigned base = stA + (unsigned)((wm * 64 + mi * 16) * 80) + kb + aoff;
                ldsm4(af[mi][0], af[mi][1], af[mi][2], af[mi][3], base);
            }
            ldsm4(bf[0][0], bf[0][1], bf[1][0], bf[1][1],
                  stB + (unsigned)((wn * 32) * 80) + kb + boff);
            ldsm4(bf[2][0], bf[2][1], bf[3][0], bf[3][1],
                  stB + (unsigned)((wn * 32 + 16) * 80) + kb + boff);
#pragma unroll
            for (int mi = 0; mi < 4; mi++)
#pragma unroll
                for (int nj = 0; nj < 4; nj++) {
                    asm volatile(
                        "mma.sync.aligned.m16n8k16.row.col.f32.f16.f16.f32 "
                        "{%0,%1,%2,%3}, {%4,%5,%6,%7}, {%8,%9}, {%0,%1,%2,%3};"
                        : "+f"(acc[mi][nj][0]), "+f"(acc[mi][nj][1]),
                          "+f"(acc[mi][nj][2]), "+f"(acc[mi][nj][3])
                        : "r"(af[mi][0]), "r"(af[mi][1]), "r"(af[mi][2]), "r"(af[mi][3]),
                          "r"(bf[nj][0]), "r"(bf[nj][1]));
                }
        }
    }

    // epilogue: bias + evict-first streaming stores (output is never re-read;
    // keeping it out of L2 preserves B-tile residency in this L2-bound GEMM)
#pragma unroll
    for (int mi = 0; mi < 4; mi++) {
        int m0 = bm + wm * 64 + mi * 16 + gid;
#pragma unroll
        for (int nj = 0; nj < 4; nj++) {
            int n0 = bn + wn * 32 + nj * 8 + tig * 2;
            if (n0 < N) {
                float b0 = bias ? bias[n0]     : 0.f;
                float b1 = bias ? bias[n0 + 1] : 0.f;
                if (m0 < M)
                    stg_cs_v2(&C[(long)m0 * N + n0], acc[mi][nj][0] + b0, acc[mi][nj][1] + b1);
                if (m0 + 8 < M)
                    stg_cs_v2(&C[(long)(m0 + 8) * N + n0], acc[mi][nj][2] + b0, acc[mi][nj][3] + b1);
            }
        }
    }
}

// ---------------- edge kernels ----------------
// Softmax is shift-invariant; |e| is O(1) here so no max-subtraction needed.

__global__ void k_edge_ex(const int* __restrict__ src, const int* __restrict__ dst) {
    long i = (long)blockIdx.x * blockDim.x + threadIdx.x;
    if (i >= (long)R_TOTAL * N_EDGES * HEADS) return;
    int h = (int)(i % HEADS);
    int e = (int)((i / HEADS) % N_EDGES);
    int r = (int)(i / ((long)HEADS * N_EDGES));
    int s = src[r * N_EDGES + e];
    int d = dst[r * N_EDGES + e];
    float ev = g_el[((long)r * N_NODES + s) * HEADS + h] +
               g_er[((long)r * N_NODES + d) * HEADS + h];
    ev = (ev >= 0.f) ? ev : NEG_SLOPE * ev;
    float ex = expf(ev);
    g_ex[i] = ex;
    atomicAdd(&g_den[((long)r * N_NODES + d) * HEADS + h], ex);
}

__global__ void k_msg(const int* __restrict__ src, const int* __restrict__ dst) {
    long gw = ((long)blockIdx.x * blockDim.x + threadIdx.x) >> 5;
    int lane = threadIdx.x & 31;
    if (gw >= (long)R_TOTAL * N_EDGES) return;
    int r = (int)(gw / N_EDGES);
    int e = (int)(gw % N_EDGES);
    int s = src[r * N_EDGES + e];
    int d = dst[r * N_EDGES + e];
    int c0 = lane * 4;
    int h = lane >> 3;
    float ex  = g_ex[gw * HEADS + h];
    float den = fmaxf(g_den[((long)r * N_NODES + d) * HEADS + h], 1e-9f);
    float a = ex / den;
    uint2 zu = *reinterpret_cast<const uint2*>(&g_z[((long)r * N_NODES + s) * DIM_OUT + c0]);
    float2 z01 = __half22float2(*reinterpret_cast<__half2*>(&zu.x));
    float2 z23 = __half22float2(*reinterpret_cast<__half2*>(&zu.y));
    float* p = &g_acc[(long)d * DIM_OUT + c0];
    asm volatile("red.global.add.v4.f32 [%0], {%1,%2,%3,%4};"
                 :: "l"(p), "f"(a * z01.x), "f"(a * z01.y), "f"(a * z23.x), "f"(a * z23.y)
                 : "memory");
}

// relu(mean) -> g_x fp16; ALSO zeroes state for the next layer
__global__ void k_finalize() {
    long i = (long)blockIdx.x * blockDim.x + threadIdx.x;
    const long NA = (long)R_TOTAL * N_NODES * HEADS;
    if (i < NA) g_den[i] = 0.0f;
    if (i >= (long)N_NODES * DIM_OUT) return;
    int n = (int)(i / DIM_OUT);
    int c = (int)(i % DIM_OUT);
    float v = g_acc[i] * (1.0f / (float)R_TOTAL);
    g_acc[i] = 0.0f;
    v = (v > 0.f) ? v : 0.f;
    g_x[(long)n * DIN + c] = __float2half_rn(v);
}

// classifier A matrices (fp16): row layout [k]
__global__ void k_buildA(const int* __restrict__ root_idx,
                         const int* __restrict__ rel,
                         const float* __restrict__ sub_rel_emb,
                         const float* __restrict__ obj_rel_emb) {
    long i = (long)blockIdx.x * blockDim.x + threadIdx.x;
    if (i >= (long)2 * BATCH * KCLS) return;
    int k = (int)(i % KCLS);
    int row = (int)(i / KCLS);
    int z = row >> 10;          // 0 = sub_pred inputs, 1 = obj_pred inputs
    int b = row & 1023;
    __half v;
    if (k < DIM_OUT) {
        int node = root_idx[z == 0 ? BATCH + b : b];
        v = g_x[(long)node * DIN + k];
    } else {
        const float* re = (z == 0) ? obj_rel_emb : sub_rel_emb;
        v = __float2half_rn(re[rel[b] * DIM_R + (k - DIM_OUT)]);
    }
    g_A[i] = v;
}

// ---------------- launch ----------------
extern "C" void kernel_launch(void* const* d_in, const int* in_sizes, int n_in,
                              void* d_out, int out_size) {
    const int*   node_ids    = (const int*)d_in[0];
    const int*   edge_src    = (const int*)d_in[1];
    const int*   edge_dst    = (const int*)d_in[2];
    const int*   root_idx    = (const int*)d_in[3];
    const int*   rel         = (const int*)d_in[4];
    const float* entity_emb  = (const float*)d_in[5];
    const float* basis_freq  = (const float*)d_in[6];
    const float* phase       = (const float*)d_in[7];
    const float* fc_w        = (const float*)d_in[8];
    const float* attn_l      = (const float*)d_in[9];
    const float* attn_r      = (const float*)d_in[10];
    const float* sub_rel_emb = (const float*)d_in[11];
    const float* obj_rel_emb = (const float*)d_in[12];
    const float* sub_cls_w   = (const float*)d_in[13];
    const float* sub_cls_b   = (const float*)d_in[14];
    const float* obj_cls_w   = (const float*)d_in[15];
    const float* obj_cls_b   = (const float*)d_in[16];
    const int*   ts_ptr      = (n_in > 17) ? (const int*)d_in[17] : nullptr;

    float* out = (float*)d_out;

    __half *px, *pA, *pw, *pcw, *pz;
    float *pel, *per;
    cudaGetSymbolAddress((void**)&px, g_x);
    cudaGetSymbolAddress((void**)&pz, g_z);
    cudaGetSymbolAddress((void**)&pA, g_A);
    cudaGetSymbolAddress((void**)&pel, g_el);
    cudaGetSymbolAddress((void**)&per, g_er);
    cudaGetSymbolAddress((void**)&pw, g_w);
    cudaGetSymbolAddress((void**)&pcw, g_cw);

    static int smem_set = 0;
    if (!smem_set) {
        cudaFuncSetAttribute(zgemm, cudaFuncAttributeMaxDynamicSharedMemorySize, SMEM_Z);
        cudaFuncSetAttribute(hgemm, cudaFuncAttributeMaxDynamicSharedMemorySize, SMEM_GEMM);
        smem_set = 1;
    }

    const int TB = 256;
    long n_init = (long)N_NODES * DIN;
    k_init<<<(unsigned)((n_init + TB - 1) / TB), TB>>>(node_ids, entity_emb, basis_freq, phase, ts_ptr);
    long n_pw = (long)2 * R_TOTAL * DIN * DIM_OUT;
    k_prep_w<<<(unsigned)((n_pw + TB - 1) / TB), TB>>>(fc_w);
    dim3 gcw(NPAD / 32, KCLS / 32, 2);
    k_prep_cw<<<gcw, dim3(32, 8)>>>(sub_cls_w, obj_cls_w);

    const long n_edgehead = (long)R_TOTAL * N_EDGES * HEADS;
    const long n_zero     = (long)N_NODES * DIM_OUT;
    const long n_msgw     = (long)R_TOTAL * N_EDGES * 32;

    for (int l = 0; l < 2; l++) {
        dim3 gz(1, (N_NODES + 127) / 128, NGRP);
        zgemm<<<gz, 256, SMEM_Z>>>(px,
                            pw + (long)l * R_TOTAL * DIM_OUT * DIN,
                            pz,
                            attn_l + (long)l * R_TOTAL * HEADS * DHEAD,
                            attn_r + (long)l * R_TOTAL * HEADS * DHEAD,
                            pel, per);

        k_edge_ex<<<(unsigned)((n_edgehead + TB - 1) / TB), TB>>>(edge_src, edge_dst);
        k_msg<<<(unsigned)((n_msgw + TB - 1) / TB), TB>>>(edge_src, edge_dst);

        k_finalize<<<(unsigned)((n_zero + TB - 1) / TB), TB>>>();
    }

    long n_bA = (long)2 * BATCH * KCLS;
    k_buildA<<<(unsigned)((n_bA + TB - 1) / TB), TB>>>(root_idx, rel, sub_rel_emb, obj_rel_emb);

    // classifier: both z in one launch; grid (235, 8, 2)
    dim3 gc(NPAD / 128, BATCH / 128, 2);
    hgemm<<<gc, 256, SMEM_GEMM>>>(pA, (long)BATCH * KCLS,
                        pcw, (long)NPAD * KCLS,
                        out, (long)BATCH * NUME,
                        sub_cls_b, obj_cls_b, BATCH, NUME, KCLS);
    (void)in_sizes; (void)out_size;
}